// round 16
// baseline (speedup 1.0000x reference)
#include <cuda_runtime.h>
#include <math.h>

// ---------------------------------------------------------------------------
// CrossViT block: B=1, N=196, EMB=256, H=8, DH=32, HID=1024
// Streams: s=0 = vis, s=1 = ir.
//   nv = LN1(x_s);  qkv_s = x_s @ Wqkv_s + b
//   cross_s = softmax(q_s k_{1-s}^T / 16) v_{1-s}  (per head)
//   r_s = nv + cross_s @ Wp_s + bp_s
//   lv_s = LN2(r_s);  o_s = gelu(lv W1 + b1) W2 + b2 + lv
//   out = concat(recon(o_ir), recon(o_vis))  -> (1,2,224,224) fp32
// ---------------------------------------------------------------------------

#define NTOK 196
#define EMB  256
#define HID  1024
#define QKVN 768

// device scratch (allocation-free rule: __device__ globals)
__device__ float g_qkv[2 * NTOK * QKVN];
__device__ float g_att[2 * NTOK * EMB];
__device__ float g_r  [2 * NTOK * EMB];
__device__ float g_lv [2 * NTOK * EMB];
__device__ float g_h  [2 * NTOK * HID];

__device__ __forceinline__ float warp_sum(float v) {
    #pragma unroll
    for (int o = 16; o > 0; o >>= 1) v += __shfl_xor_sync(0xffffffffu, v, o);
    return v;
}

__device__ __forceinline__ int recon_idx(int s, int n, int e) {
    // x(B,196,256) -> (14,14,16,16) -> transpose(a,b,i,j) -> flat 224*224
    int i = n / 14, j = n % 14;
    int a = e >> 4, b = e & 15;
    int ch = 1 - s;  // channel 0 = ir stream, channel 1 = vis stream
    return ch * 50176 + ((a * 16 + b) * 14 + i) * 14 + j;
}

// ---------------------------------------------------------------------------
// LayerNorm over EMB=256, one row per block (256 threads).
// Writes o = LN(x)*w + b (+ extra_bias if non-null, used to pre-seed residual)
// ---------------------------------------------------------------------------
__global__ void ln_kern(const float* __restrict__ x0, const float* __restrict__ x1,
                        const float* __restrict__ w0, const float* __restrict__ b0,
                        const float* __restrict__ w1, const float* __restrict__ b1,
                        float* __restrict__ o0, float* __restrict__ o1,
                        const float* __restrict__ e0, const float* __restrict__ e1)
{
    int s = blockIdx.y;
    const float* x = s ? x1 : x0;
    const float* w = s ? w1 : w0;
    const float* b = s ? b1 : b0;
    const float* e = s ? e1 : e0;
    float* o = s ? o1 : o0;

    int row = blockIdx.x;
    int tid = threadIdx.x;
    int lane = tid & 31, warp = tid >> 5;

    float v = x[row * EMB + tid];

    __shared__ float red[8];
    __shared__ float stat[2];

    float su = warp_sum(v);
    if (lane == 0) red[warp] = su;
    __syncthreads();
    if (tid < 32) {
        float t = (lane < 8) ? red[lane] : 0.f;
        t = warp_sum(t);
        if (lane == 0) stat[0] = t * (1.0f / EMB);
    }
    __syncthreads();
    float mean = stat[0];
    float d = v - mean;
    __syncthreads();

    float sq = warp_sum(d * d);
    if (lane == 0) red[warp] = sq;
    __syncthreads();
    if (tid < 32) {
        float t = (lane < 8) ? red[lane] : 0.f;
        t = warp_sum(t);
        if (lane == 0) stat[1] = t * (1.0f / EMB);
    }
    __syncthreads();
    float var = stat[1];

    float out = d * rsqrtf(var + 1e-5f) * w[tid] + b[tid];
    if (e) out += e[tid];
    o[row * EMB + tid] = out;
}

// ---------------------------------------------------------------------------
// Generic skinny GEMM: C[196 x N] = A[196 x K] @ W[K x N] (+bias) (+epilogue)
// Tile: 49 rows x 32 cols, 256 threads (32 col-lanes x 8 row-groups, 7 rows/thread).
// A chunk staged k-major in smem (pad 57: conflict-free store & broadcast read).
// grid: (N/32, 4, 2*KS)  z -> (stream, k-split)
// ---------------------------------------------------------------------------
struct GA { const float* A; const float* W; const float* Bi; float* C; };

#define MODE_STORE  0
#define MODE_GELU   1
#define MODE_ATOMIC 2
#define MODE_RECON  3

template <int MODE>
__global__ void gemm_kern(GA ga0, GA ga1, int K, int N, int KS)
{
    int z = blockIdx.z;
    int s = z / KS;
    int ks = z - s * KS;
    GA g = s ? ga1 : ga0;

    int lane = threadIdx.x & 31;
    int rg   = threadIdx.x >> 5;         // 0..7
    int col  = blockIdx.x * 32 + lane;
    int row0 = blockIdx.y * 49;

    int klen = K / KS;
    int kbeg = ks * klen;

    __shared__ float As[64][57];          // [k][row], rows padded 49->56
    float acc[7] = {0.f, 0.f, 0.f, 0.f, 0.f, 0.f, 0.f};

    const float* Abase = g.A + (size_t)row0 * K;

    for (int kc = 0; kc < klen; kc += 64) {
        int kk0 = kbeg + kc;
        for (int t = threadIdx.x; t < 56 * 64; t += 256) {
            int r = t >> 6;               // 0..55
            int k = t & 63;
            As[k][r] = (r < 49) ? Abase[(size_t)r * K + kk0 + k] : 0.f;
        }
        __syncthreads();

        const float* wp = g.W + (size_t)kk0 * N + col;
        #pragma unroll 8
        for (int k = 0; k < 64; k++) {
            float w = *wp; wp += N;
            const float* as = &As[k][rg];
            acc[0] += as[0]  * w;
            acc[1] += as[8]  * w;
            acc[2] += as[16] * w;
            acc[3] += as[24] * w;
            acc[4] += as[32] * w;
            acc[5] += as[40] * w;
            acc[6] += as[48] * w;
        }
        __syncthreads();
    }

    float bias = (MODE == MODE_STORE || MODE == MODE_GELU) ? g.Bi[col] : 0.f;

    #pragma unroll
    for (int i = 0; i < 7; i++) {
        int r = rg + 8 * i;
        if (r < 49) {
            int row = row0 + r;
            float v = acc[i] + bias;
            if (MODE == MODE_STORE) {
                g.C[(size_t)row * N + col] = v;
            } else if (MODE == MODE_GELU) {
                g.C[(size_t)row * N + col] = 0.5f * v * (1.0f + erff(v * 0.70710678118f));
            } else if (MODE == MODE_ATOMIC) {
                atomicAdd(&g.C[(size_t)row * N + col], acc[i]);
            } else { // MODE_RECON: accumulate into reconstructed output pixels
                atomicAdd(&g.C[recon_idx(s, row, col)], acc[i]);
            }
        }
    }
}

// ---------------------------------------------------------------------------
// Fused per-head cross attention.
// grid: (7 query-tiles of 28, 16 = stream*8 + head), 256 threads.
// K/V for head staged in dynamic smem (pad 33 -> conflict free).
// Warp handles one query at a time: lanes own keys for scores/softmax,
// lanes own output dims for the PV product.
// ---------------------------------------------------------------------------
__global__ void attn_kern(const float* __restrict__ qkv0, const float* __restrict__ qkv1,
                          float* __restrict__ o0, float* __restrict__ o1)
{
    extern __shared__ float sm[];
    float* Ks = sm;                 // 196*33
    float* Vs = sm + NTOK * 33;     // 196*33
    float* Ps = Vs + NTOK * 33;     // 8*224

    int sh = blockIdx.y;
    int s = sh >> 3;
    int h = sh & 7;
    const float* Q  = s ? qkv1 : qkv0;
    const float* KV = s ? qkv0 : qkv1;   // cross: q_s attends k/v of other stream
    float* O = s ? o1 : o0;

    int tid = threadIdx.x;
    for (int t = tid; t < NTOK * 32; t += 256) {
        int n = t >> 5, d = t & 31;
        const float* p = KV + (size_t)n * QKVN + h * 96 + d * 3;
        Ks[n * 33 + d] = p[1];
        Vs[n * 33 + d] = p[2];
    }
    __syncthreads();

    int warp = tid >> 5, lane = tid & 31;
    int qbase = blockIdx.x * 28;

    for (int qq = warp; qq < 28; qq += 8) {
        int n = qbase + qq;
        const float* qp = Q + (size_t)n * QKVN + h * 96;
        float q[32];
        #pragma unroll
        for (int d = 0; d < 32; d++) q[d] = qp[d * 3];

        float sc[7];
        float mx = -1e30f;
        #pragma unroll
        for (int j = 0; j < 7; j++) {
            int kk = lane + 32 * j;
            float dot = -1e30f;
            if (kk < NTOK) {
                const float* kr = &Ks[kk * 33];
                float acc = 0.f;
                #pragma unroll
                for (int d = 0; d < 32; d++) acc += q[d] * kr[d];
                dot = acc * (1.0f / 16.0f);
            }
            sc[j] = dot;
            mx = fmaxf(mx, dot);
        }
        #pragma unroll
        for (int o = 16; o > 0; o >>= 1) mx = fmaxf(mx, __shfl_xor_sync(0xffffffffu, mx, o));

        float sum = 0.f;
        #pragma unroll
        for (int j = 0; j < 7; j++) {
            int kk = lane + 32 * j;
            float e = (kk < NTOK) ? __expf(sc[j] - mx) : 0.f;
            Ps[warp * 224 + kk] = e;
            sum += e;
        }
        sum = warp_sum(sum);
        float inv = 1.0f / sum;
        __syncwarp();

        float acc = 0.f;
        const float* ps = &Ps[warp * 224];
        #pragma unroll 4
        for (int kk = 0; kk < NTOK; kk++)
            acc += ps[kk] * Vs[kk * 33 + lane];

        O[(size_t)n * EMB + h * 32 + lane] = acc * inv;
        __syncwarp();
    }
}

// ---------------------------------------------------------------------------
// Seed d_out with lv + b2 through the recon permutation (FF2 accumulates on top)
// ---------------------------------------------------------------------------
__global__ void init_out_kern(const float* __restrict__ lv0, const float* __restrict__ lv1,
                              const float* __restrict__ b20, const float* __restrict__ b21,
                              float* __restrict__ out)
{
    int s = blockIdx.y;
    int n = blockIdx.x;
    int c = threadIdx.x;
    const float* lv = s ? lv1 : lv0;
    const float* b2 = s ? b21 : b20;
    float v = lv[n * EMB + c] + b2[c];
    out[recon_idx(s, n, c)] = v;
}

// ---------------------------------------------------------------------------
// host launch
// ---------------------------------------------------------------------------
extern "C" void kernel_launch(void* const* d_in, const int* in_sizes, int n_in,
                              void* d_out, int out_size)
{
    const float* vis    = (const float*)d_in[0];
    const float* ir     = (const float*)d_in[1];
    const float* ln1v_w = (const float*)d_in[2];
    const float* ln1v_b = (const float*)d_in[3];
    const float* ln1i_w = (const float*)d_in[4];
    const float* ln1i_b = (const float*)d_in[5];
    const float* ln2v_w = (const float*)d_in[6];
    const float* ln2v_b = (const float*)d_in[7];
    const float* ln2i_w = (const float*)d_in[8];
    const float* ln2i_b = (const float*)d_in[9];
    const float* Wqkv_v = (const float*)d_in[10];
    const float* bqkv_v = (const float*)d_in[11];
    const float* Wqkv_i = (const float*)d_in[12];
    const float* bqkv_i = (const float*)d_in[13];
    const float* Wp_v   = (const float*)d_in[14];
    const float* bp_v   = (const float*)d_in[15];
    const float* Wp_i   = (const float*)d_in[16];
    const float* bp_i   = (const float*)d_in[17];
    const float* W1v    = (const float*)d_in[18];
    const float* b1v    = (const float*)d_in[19];
    const float* W2v    = (const float*)d_in[20];
    const float* b2v    = (const float*)d_in[21];
    const float* W1i    = (const float*)d_in[22];
    const float* b1i    = (const float*)d_in[23];
    const float* W2i    = (const float*)d_in[24];
    const float* b2i    = (const float*)d_in[25];

    float* out = (float*)d_out;

    float *qkvB, *attB, *rB, *lvB, *hB;
    cudaGetSymbolAddress((void**)&qkvB, g_qkv);
    cudaGetSymbolAddress((void**)&attB, g_att);
    cudaGetSymbolAddress((void**)&rB,   g_r);
    cudaGetSymbolAddress((void**)&lvB,  g_lv);
    cudaGetSymbolAddress((void**)&hB,   g_h);

    float* qkv0 = qkvB;               float* qkv1 = qkvB + NTOK * QKVN;
    float* att0 = attB;               float* att1 = attB + NTOK * EMB;
    float* r0   = rB;                 float* r1   = rB   + NTOK * EMB;
    float* lv0  = lvB;                float* lv1  = lvB  + NTOK * EMB;
    float* h0   = hB;                 float* h1   = hB   + NTOK * HID;

    const int ATTN_SMEM = (2 * NTOK * 33 + 8 * 224) * (int)sizeof(float); // 58912 B
    cudaFuncSetAttribute(attn_kern, cudaFuncAttributeMaxDynamicSharedMemorySize, ATTN_SMEM);

    // 1. LN1 -> r = LN1(x) + bproj  (seeds residual for atomic proj GEMM)
    ln_kern<<<dim3(NTOK, 2), 256>>>(vis, ir, ln1v_w, ln1v_b, ln1i_w, ln1i_b,
                                    r0, r1, bp_v, bp_i);

    // 2. QKV = x @ Wqkv + b  (both streams)
    {
        GA a0{vis, Wqkv_v, bqkv_v, qkv0};
        GA a1{ir,  Wqkv_i, bqkv_i, qkv1};
        gemm_kern<MODE_STORE><<<dim3(QKVN / 32, 4, 2), 256>>>(a0, a1, EMB, QKVN, 1);
    }

    // 3. Cross attention (fused per head)
    attn_kern<<<dim3(7, 16), 256, ATTN_SMEM>>>(qkv0, qkv1, att0, att1);

    // 4. r += att @ Wp  (split-K=2, atomic)
    {
        GA a0{att0, Wp_v, nullptr, r0};
        GA a1{att1, Wp_i, nullptr, r1};
        gemm_kern<MODE_ATOMIC><<<dim3(EMB / 32, 4, 4), 256>>>(a0, a1, EMB, EMB, 2);
    }

    // 5. LN2 -> lv
    ln_kern<<<dim3(NTOK, 2), 256>>>(r0, r1, ln2v_w, ln2v_b, ln2i_w, ln2i_b,
                                    lv0, lv1, nullptr, nullptr);

    // 6. h = gelu(lv @ W1 + b1)
    {
        GA a0{lv0, W1v, b1v, h0};
        GA a1{lv1, W1i, b1i, h1};
        gemm_kern<MODE_GELU><<<dim3(HID / 32, 4, 2), 256>>>(a0, a1, EMB, HID, 1);
    }

    // 7. out = recon(lv + b2)
    init_out_kern<<<dim3(NTOK, 2), 256>>>(lv0, lv1, b2v, b2i, out);

    // 8. out += recon(h @ W2)  (split-K=4, atomic into recon'd pixels)
    {
        GA a0{h0, W2v, nullptr, out};
        GA a1{h1, W2i, nullptr, out};
        gemm_kern<MODE_RECON><<<dim3(EMB / 32, 4, 8), 256>>>(a0, a1, HID, EMB, 4);
    }
}

// round 17
// speedup vs baseline: 1.2129x; 1.2129x over previous
#include <cuda_runtime.h>
#include <math.h>
#include <stdint.h>

// ---------------------------------------------------------------------------
// CrossViT block: B=1, N=196, EMB=256, H=8, DH=32, HID=1024
//   nv = LN1(x_s);  qkv_s = x_s @ Wqkv_s + b
//   cross_s = softmax(q_s k_{1-s}^T / 16) v_{1-s}  (per head)
//   r_s = nv + cross_s @ Wp_s + bp_s
//   lv_s = LN2(r_s);  o_s = gelu(lv W1 + b1) W2 + b2 + lv
//   out = concat(recon(o_ir), recon(o_vis))  -> (1,2,224,224) fp32
// ---------------------------------------------------------------------------

#define NTOK 196
#define EMB  256
#define HID  1024
#define QKVN 768

__device__ float g_qkv[2 * NTOK * QKVN];
__device__ float g_att[2 * NTOK * EMB];
__device__ float g_r  [2 * NTOK * EMB];
__device__ float g_lv [2 * NTOK * EMB];
__device__ float g_h  [2 * NTOK * HID];

__device__ __forceinline__ float warp_sum(float v) {
    #pragma unroll
    for (int o = 16; o > 0; o >>= 1) v += __shfl_xor_sync(0xffffffffu, v, o);
    return v;
}

__device__ __forceinline__ int recon_idx(int s, int n, int e) {
    int i = n / 14, j = n % 14;
    int a = e >> 4, b = e & 15;
    int ch = 1 - s;  // channel 0 = ir stream, channel 1 = vis stream
    return ch * 50176 + ((a * 16 + b) * 14 + i) * 14 + j;
}

__device__ __forceinline__ uint32_t smem_u32(const void* p) {
    return (uint32_t)__cvta_generic_to_shared(p);
}
__device__ __forceinline__ void cpasync4(uint32_t s, const float* g) {
    asm volatile("cp.async.ca.shared.global [%0], [%1], 4;\n" :: "r"(s), "l"(g));
}

// ---------------------------------------------------------------------------
// LayerNorm over EMB=256, one row per block (256 threads).
// o = LN(x)*w + b (+extra bias e).  If RECON, also writes out = o + bb at the
// pixel-shuffled output position (fuses the output-init pass).
// ---------------------------------------------------------------------------
template <int RECON>
__global__ void ln_kern(const float* __restrict__ x0, const float* __restrict__ x1,
                        const float* __restrict__ w0, const float* __restrict__ b0,
                        const float* __restrict__ w1, const float* __restrict__ b1,
                        float* __restrict__ o0, float* __restrict__ o1,
                        const float* __restrict__ e0, const float* __restrict__ e1,
                        const float* __restrict__ bb0, const float* __restrict__ bb1,
                        float* __restrict__ outbuf)
{
    int s = blockIdx.y;
    const float* x = s ? x1 : x0;
    const float* w = s ? w1 : w0;
    const float* b = s ? b1 : b0;
    const float* e = s ? e1 : e0;
    float* o = s ? o1 : o0;

    int row = blockIdx.x;
    int tid = threadIdx.x;
    int lane = tid & 31, warp = tid >> 5;

    float v = x[row * EMB + tid];

    __shared__ float red[8];
    __shared__ float stat[2];

    float su = warp_sum(v);
    if (lane == 0) red[warp] = su;
    __syncthreads();
    if (tid < 32) {
        float t = (lane < 8) ? red[lane] : 0.f;
        t = warp_sum(t);
        if (lane == 0) stat[0] = t * (1.0f / EMB);
    }
    __syncthreads();
    float mean = stat[0];
    float d = v - mean;
    __syncthreads();

    float sq = warp_sum(d * d);
    if (lane == 0) red[warp] = sq;
    __syncthreads();
    if (tid < 32) {
        float t = (lane < 8) ? red[lane] : 0.f;
        t = warp_sum(t);
        if (lane == 0) stat[1] = t * (1.0f / EMB);
    }
    __syncthreads();
    float var = stat[1];

    float out = d * rsqrtf(var + 1e-5f) * w[tid] + b[tid];
    if (e) out += e[tid];
    o[row * EMB + tid] = out;

    if (RECON) {
        const float* bb = s ? bb1 : bb0;
        outbuf[recon_idx(s, row, tid)] = out + bb[tid];
    }
}

// ---------------------------------------------------------------------------
// Skinny GEMM: C[196 x N] = A[196 x K] @ W[K x N] (+bias/epilogue)
// Tile: 49 rows x 32 cols, 256 threads (lane = col, warp = row-group of 7).
// A and W chunks staged in smem via cp.async with double buffering.
// Inner loop: 1 W-LDS (conflict-free) + 7 broadcast A-LDS + 7 FFMA per k.
// grid: (N/32, 4, 2*KS)  z -> (stream, k-split)
// ---------------------------------------------------------------------------
struct GA { const float* A; const float* W; const float* Bi; float* C; };

#define MODE_STORE  0
#define MODE_GELU   1
#define MODE_ATOMIC 2
#define MODE_RECON  3

template <int MODE>
__global__ void __launch_bounds__(256) gemm_kern(GA ga0, GA ga1, int K, int N, int KS)
{
    int z = blockIdx.z;
    int s = z / KS;
    int ks = z - s * KS;
    GA g = s ? ga1 : ga0;

    int lane = threadIdx.x & 31;
    int warp = threadIdx.x >> 5;          // 0..7
    int col  = blockIdx.x * 32 + lane;
    int row0 = blockIdx.y * 49;

    int klen = K / KS;
    int kbeg = ks * klen;
    int nc   = klen >> 6;                 // chunks of 64 k

    __shared__ float As[2][64][57];       // [buf][k][row]
    __shared__ float Ws[2][64][33];       // [buf][k][col]

    const float* Abase = g.A + (size_t)row0 * K + kbeg;
    const float* Wbase = g.W + (size_t)kbeg * N + blockIdx.x * 32;

    float acc[7] = {0.f, 0.f, 0.f, 0.f, 0.f, 0.f, 0.f};

    // ---- stage chunk c into buffer buf ----
    auto stage = [&](int buf, int c) {
        int k0 = c * 64;
        #pragma unroll 4
        for (int t = threadIdx.x; t < 49 * 64; t += 256) {
            int r = t >> 6, k = t & 63;   // k fastest -> coalesced global reads
            cpasync4(smem_u32(&As[buf][k][r]), Abase + (size_t)r * K + k0 + k);
        }
        #pragma unroll 4
        for (int t = threadIdx.x; t < 64 * 32; t += 256) {
            int k = t >> 5, c2 = t & 31;  // col fastest -> coalesced
            cpasync4(smem_u32(&Ws[buf][k][c2]), Wbase + (size_t)(k0 + k) * N + c2);
        }
    };

    stage(0, 0);
    asm volatile("cp.async.commit_group;\n");

    for (int c = 0; c < nc; c++) {
        int buf = c & 1;
        if (c + 1 < nc) {
            stage(buf ^ 1, c + 1);
            asm volatile("cp.async.commit_group;\n");
            asm volatile("cp.async.wait_group 1;\n" ::: "memory");
        } else {
            asm volatile("cp.async.wait_group 0;\n" ::: "memory");
        }
        __syncthreads();

        #pragma unroll 8
        for (int k = 0; k < 64; k++) {
            float w = Ws[buf][k][lane];
            const float* as = &As[buf][k][warp];
            acc[0] += as[0]  * w;
            acc[1] += as[8]  * w;
            acc[2] += as[16] * w;
            acc[3] += as[24] * w;
            acc[4] += as[32] * w;
            acc[5] += as[40] * w;
            acc[6] += as[48] * w;
        }
        __syncthreads();
    }

    float bias = (MODE == MODE_STORE || MODE == MODE_GELU) ? g.Bi[col] : 0.f;

    #pragma unroll
    for (int i = 0; i < 7; i++) {
        int r = warp + 8 * i;
        if (r < 49) {
            int row = row0 + r;
            float v = acc[i] + bias;
            if (MODE == MODE_STORE) {
                g.C[(size_t)row * N + col] = v;
            } else if (MODE == MODE_GELU) {
                g.C[(size_t)row * N + col] = 0.5f * v * (1.0f + erff(v * 0.70710678118f));
            } else if (MODE == MODE_ATOMIC) {
                atomicAdd(&g.C[(size_t)row * N + col], acc[i]);
            } else { // MODE_RECON: accumulate into reconstructed output pixels
                atomicAdd(&g.C[recon_idx(s, row, col)], acc[i]);
            }
        }
    }
}

// ---------------------------------------------------------------------------
// Fused per-head cross attention.
// grid: (7 query-tiles of 28, 16 = stream*8 + head), 256 threads.
// ---------------------------------------------------------------------------
__global__ void attn_kern(const float* __restrict__ qkv0, const float* __restrict__ qkv1,
                          float* __restrict__ o0, float* __restrict__ o1)
{
    extern __shared__ float sm[];
    float* Ks = sm;                 // 196*33
    float* Vs = sm + NTOK * 33;     // 196*33
    float* Ps = Vs + NTOK * 33;     // 8*224

    int sh = blockIdx.y;
    int s = sh >> 3;
    int h = sh & 7;
    const float* Q  = s ? qkv1 : qkv0;
    const float* KV = s ? qkv0 : qkv1;   // cross: q_s attends k/v of other stream
    float* O = s ? o1 : o0;

    int tid = threadIdx.x;
    for (int t = tid; t < NTOK * 32; t += 256) {
        int n = t >> 5, d = t & 31;
        const float* p = KV + (size_t)n * QKVN + h * 96 + d * 3;
        Ks[n * 33 + d] = p[1];
        Vs[n * 33 + d] = p[2];
    }
    __syncthreads();

    int warp = tid >> 5, lane = tid & 31;
    int qbase = blockIdx.x * 28;

    for (int qq = warp; qq < 28; qq += 8) {
        int n = qbase + qq;
        const float* qp = Q + (size_t)n * QKVN + h * 96;
        float q[32];
        #pragma unroll
        for (int d = 0; d < 32; d++) q[d] = qp[d * 3];

        float sc[7];
        float mx = -1e30f;
        #pragma unroll
        for (int j = 0; j < 7; j++) {
            int kk = lane + 32 * j;
            float dot = -1e30f;
            if (kk < NTOK) {
                const float* kr = &Ks[kk * 33];
                float acc = 0.f;
                #pragma unroll
                for (int d = 0; d < 32; d++) acc += q[d] * kr[d];
                dot = acc * (1.0f / 16.0f);
            }
            sc[j] = dot;
            mx = fmaxf(mx, dot);
        }
        #pragma unroll
        for (int o = 16; o > 0; o >>= 1) mx = fmaxf(mx, __shfl_xor_sync(0xffffffffu, mx, o));

        float sum = 0.f;
        #pragma unroll
        for (int j = 0; j < 7; j++) {
            int kk = lane + 32 * j;
            float e = (kk < NTOK) ? __expf(sc[j] - mx) : 0.f;
            Ps[warp * 224 + kk] = e;
            sum += e;
        }
        sum = warp_sum(sum);
        float inv = 1.0f / sum;
        __syncwarp();

        float acc = 0.f;
        const float* ps = &Ps[warp * 224];
        #pragma unroll 4
        for (int kk = 0; kk < NTOK; kk++)
            acc += ps[kk] * Vs[kk * 33 + lane];

        O[(size_t)n * EMB + h * 32 + lane] = acc * inv;
        __syncwarp();
    }
}

// ---------------------------------------------------------------------------
// host launch
// ---------------------------------------------------------------------------
extern "C" void kernel_launch(void* const* d_in, const int* in_sizes, int n_in,
                              void* d_out, int out_size)
{
    const float* vis    = (const float*)d_in[0];
    const float* ir     = (const float*)d_in[1];
    const float* ln1v_w = (const float*)d_in[2];
    const float* ln1v_b = (const float*)d_in[3];
    const float* ln1i_w = (const float*)d_in[4];
    const float* ln1i_b = (const float*)d_in[5];
    const float* ln2v_w = (const float*)d_in[6];
    const float* ln2v_b = (const float*)d_in[7];
    const float* ln2i_w = (const float*)d_in[8];
    const float* ln2i_b = (const float*)d_in[9];
    const float* Wqkv_v = (const float*)d_in[10];
    const float* bqkv_v = (const float*)d_in[11];
    const float* Wqkv_i = (const float*)d_in[12];
    const float* bqkv_i = (const float*)d_in[13];
    const float* Wp_v   = (const float*)d_in[14];
    const float* bp_v   = (const float*)d_in[15];
    const float* Wp_i   = (const float*)d_in[16];
    const float* bp_i   = (const float*)d_in[17];
    const float* W1v    = (const float*)d_in[18];
    const float* b1v    = (const float*)d_in[19];
    const float* W2v    = (const float*)d_in[20];
    const float* b2v    = (const float*)d_in[21];
    const float* W1i    = (const float*)d_in[22];
    const float* b1i    = (const float*)d_in[23];
    const float* W2i    = (const float*)d_in[24];
    const float* b2i    = (const float*)d_in[25];

    float* out = (float*)d_out;

    float *qkvB, *attB, *rB, *lvB, *hB;
    cudaGetSymbolAddress((void**)&qkvB, g_qkv);
    cudaGetSymbolAddress((void**)&attB, g_att);
    cudaGetSymbolAddress((void**)&rB,   g_r);
    cudaGetSymbolAddress((void**)&lvB,  g_lv);
    cudaGetSymbolAddress((void**)&hB,   g_h);

    float* qkv0 = qkvB;               float* qkv1 = qkvB + NTOK * QKVN;
    float* att0 = attB;               float* att1 = attB + NTOK * EMB;
    float* r0   = rB;                 float* r1   = rB   + NTOK * EMB;
    float* lv0  = lvB;                float* lv1  = lvB  + NTOK * EMB;
    float* h0   = hB;                 float* h1   = hB   + NTOK * HID;

    const int ATTN_SMEM = (2 * NTOK * 33 + 8 * 224) * (int)sizeof(float); // 58912 B
    cudaFuncSetAttribute(attn_kern, cudaFuncAttributeMaxDynamicSharedMemorySize, ATTN_SMEM);

    // 1. LN1 -> r = LN1(x) + bproj  (seeds residual for atomic proj GEMM)
    ln_kern<0><<<dim3(NTOK, 2), 256>>>(vis, ir, ln1v_w, ln1v_b, ln1i_w, ln1i_b,
                                       r0, r1, bp_v, bp_i,
                                       nullptr, nullptr, nullptr);

    // 2. QKV = x @ Wqkv + b  (both streams)
    {
        GA a0{vis, Wqkv_v, bqkv_v, qkv0};
        GA a1{ir,  Wqkv_i, bqkv_i, qkv1};
        gemm_kern<MODE_STORE><<<dim3(QKVN / 32, 4, 2), 256>>>(a0, a1, EMB, QKVN, 1);
    }

    // 3. Cross attention (fused per head)
    attn_kern<<<dim3(7, 16), 256, ATTN_SMEM>>>(qkv0, qkv1, att0, att1);

    // 4. r += att @ Wp  (split-K=4, atomic)
    {
        GA a0{att0, Wp_v, nullptr, r0};
        GA a1{att1, Wp_i, nullptr, r1};
        gemm_kern<MODE_ATOMIC><<<dim3(EMB / 32, 4, 8), 256>>>(a0, a1, EMB, EMB, 4);
    }

    // 5. LN2 -> lv, and seed out = recon(lv + b2)
    ln_kern<1><<<dim3(NTOK, 2), 256>>>(r0, r1, ln2v_w, ln2v_b, ln2i_w, ln2i_b,
                                       lv0, lv1, nullptr, nullptr,
                                       b2v, b2i, out);

    // 6. h = gelu(lv @ W1 + b1)
    {
        GA a0{lv0, W1v, b1v, h0};
        GA a1{lv1, W1i, b1i, h1};
        gemm_kern<MODE_GELU><<<dim3(HID / 32, 4, 2), 256>>>(a0, a1, EMB, HID, 1);
    }

    // 7. out += recon(h @ W2)  (split-K=4, atomic into recon'd pixels)
    {
        GA a0{h0, W2v, nullptr, out};
        GA a1{h1, W2i, nullptr, out};
        gemm_kern<MODE_RECON><<<dim3(EMB / 32, 4, 8), 256>>>(a0, a1, HID, EMB, 4);
    }
}